// round 15
// baseline (speedup 1.0000x reference)
#include <cuda_runtime.h>
#include <math.h>

// ---------------- problem constants ----------------
#define BATCH   32
#define DMODEL  4096
#define NH      32
#define NKV     8
#define GQ      4           // NH / NKV
#define HD      128
#define MAXSEQ  2048
#define BLKSZ   16
#define MAXBLK  128         // MAXSEQ / BLKSZ
#define ATT_SCALE 0.08838834764831845f   // 128^-0.5

#define NQKV    (NH*HD + 2*NKV*HD)       // 6144
#define SPLITS  4
#define NCHUNK  16

typedef unsigned long long ULL;

// ---------------- scratch (device globals; no allocation allowed) --------
__device__ float g_xT[DMODEL * BATCH];                    // xT[k][b]
__device__ float g_qkvT[SPLITS][NQKV * BATCH];            // partial, col-major [col][b]
__device__ float g_q[BATCH * NH * HD];                    // rope'd q, [b][h][d]
__device__ float g_knew[BATCH * NKV * HD];
__device__ float g_vnew[BATCH * NKV * HD];
__device__ float g_pm[BATCH * NH * NCHUNK];
__device__ float g_pl[BATCH * NH * NCHUNK];
__device__ float g_pacc[BATCH * NH * NCHUNK * HD];
__device__ float g_attnT[DMODEL * BATCH];                 // [h*128+d][b]
__device__ float g_oT[SPLITS][DMODEL * BATCH];            // Wo partials, [n][b]

// ---------------- packed f32x2 helpers (sm_103a) --------------------------
__device__ __forceinline__ void ffma2(ULL& acc, ULL a, ULL b) {
    asm("fma.rn.f32x2 %0, %1, %2, %3;" : "=l"(acc) : "l"(a), "l"(b), "l"(acc));
}
__device__ __forceinline__ ULL fma2v(ULL a, ULL b, ULL c) {   // a*b + c
    ULL d; asm("fma.rn.f32x2 %0, %1, %2, %3;" : "=l"(d) : "l"(a), "l"(b), "l"(c));
    return d;
}
__device__ __forceinline__ ULL mul2(ULL a, ULL b) {
    ULL d; asm("mul.rn.f32x2 %0, %1, %2;" : "=l"(d) : "l"(a), "l"(b));
    return d;
}
__device__ __forceinline__ ULL bcast2(float w) {
    ULL r; asm("mov.b64 %0, {%1, %1};" : "=l"(r) : "r"(__float_as_uint(w)));
    return r;
}
__device__ __forceinline__ void add2(ULL& a, ULL b) {
    asm("add.rn.f32x2 %0, %1, %2;" : "=l"(a) : "l"(a), "l"(b));
}
__device__ __forceinline__ ULL pack2(float a, float b) {
    ULL r; asm("mov.b64 %0, {%1, %2};" : "=l"(r)
               : "r"(__float_as_uint(a)), "r"(__float_as_uint(b)));
    return r;
}
__device__ __forceinline__ void unpack2(ULL v, float& a, float& b) {
    unsigned int x, y;
    asm("mov.b64 {%0, %1}, %2;" : "=r"(x), "=r"(y) : "l"(v));
    a = __uint_as_float(x); b = __uint_as_float(y);
}

// ---------------- cp.async helpers ----------------------------------------
__device__ __forceinline__ void cpasync16(void* smem, const void* gmem) {
    unsigned int s = (unsigned int)__cvta_generic_to_shared(smem);
    asm volatile("cp.async.cg.shared.global [%0], [%1], 16;" :: "r"(s), "l"(gmem));
}
__device__ __forceinline__ void cpcommit() {
    asm volatile("cp.async.commit_group;");
}
template<int N> __device__ __forceinline__ void cpwait() {
    asm volatile("cp.async.wait_group %0;" :: "n"(N));
}

// ---------------- 1) transpose x (32 x 4096) -> xT (4096 x 32) -----------
__global__ void transpose_x_kernel(const float* __restrict__ x) {
    __shared__ float tile[32][33];
    int k0 = blockIdx.x * 32;
    int tx = threadIdx.x;            // 0..31
    int ty = threadIdx.y;            // 0..7
    #pragma unroll
    for (int r = ty; r < 32; r += 8)
        tile[r][tx] = x[r * DMODEL + k0 + tx];
    __syncthreads();
    #pragma unroll
    for (int r = ty; r < 32; r += 8)
        g_xT[(k0 + r) * BATCH + tx] = tile[tx][r];
}

// ---------------- 2) GEMM body: Y(32 x N) = x(32 x K) @ W(K x N) ---------
// xT: [K][32]. CTA: 64 cols x one K-split, 256 threads.
// thread = (nc 0..31, kr 0..3, bh 0..1): cols n0=base+nc and n0+32,
// batches bh*16..bh*16+15 (8 f32x2 pairs). ~75 regs/thread — no spill,
// 3 CTAs/SM. Weights prefetched 16-at-a-time; FFMA2-rate bound.
#define GT  256
#define GBK 128

__device__ __forceinline__ void gemm_body(
    const float* __restrict__ xT, const float* __restrict__ W, int N,
    float* __restrict__ outT, int wcolbase, int outcolbase,
    int k0, int ksz)
{
    __shared__ __align__(16) float xs[GBK * 32];     // 16 KB
    __shared__ ULL red[2 * 2 * 32 * 8];              // 8 KB

    const int tid = threadIdx.x;
    const int nc = tid & 31;
    const int kr = (tid >> 5) & 3;
    const int bh = tid >> 7;          // 0 or 1
    const int n0 = wcolbase + nc;
    const int n1 = n0 + 32;
    const int boff = bh * 8;          // f32x2-pair offset into 16-pair batch row

    ULL acc0[8], acc1[8];
    #pragma unroll
    for (int p = 0; p < 8; p++) { acc0[p] = 0ull; acc1[p] = 0ull; }

    for (int kk = 0; kk < ksz; kk += GBK) {
        const int kbase = k0 + kk;
        __syncthreads();
        {
            const float4* src = (const float4*)(xT + (size_t)kbase * 32);
            float4* dst = (float4*)xs;
            #pragma unroll
            for (int i = tid; i < GBK * 8; i += GT) dst[i] = src[i];
        }
        __syncthreads();

        #pragma unroll
        for (int grp = 0; grp < 4; grp++) {
            // batched weight prefetch: 16 independent LDGs in flight
            float wa[8], wb[8];
            #pragma unroll
            for (int ii = 0; ii < 8; ii++) {
                const size_t row = (size_t)(kbase + kr + 4 * (8 * grp + ii)) * N;
                wa[ii] = __ldg(&W[row + n0]);
                wb[ii] = __ldg(&W[row + n1]);
            }
            #pragma unroll
            for (int ii = 0; ii < 8; ii++) {
                const int kl = kr + 4 * (8 * grp + ii);
                const ULL w0p = bcast2(wa[ii]);
                const ULL w1p = bcast2(wb[ii]);
                const ULL* xr = (const ULL*)(xs + kl * 32) + boff;
                #pragma unroll
                for (int p = 0; p < 8; p++) {
                    const ULL xp = xr[p];
                    ffma2(acc0[p], xp, w0p);
                    ffma2(acc1[p], xp, w1p);
                }
            }
        }
    }

    // reduce over kr (4 partials) via smem, for acc0 then acc1
    #pragma unroll
    for (int half = 0; half < 2; half++) {
        ULL* A = half ? acc1 : acc0;
        __syncthreads();
        if (kr >= 2) {
            ULL* d = red + ((size_t)(bh * 2 + (kr - 2)) * 32 + nc) * 8;
            #pragma unroll
            for (int p = 0; p < 8; p++) d[p] = A[p];
        }
        __syncthreads();
        if (kr < 2) {
            const ULL* s = red + ((size_t)(bh * 2 + kr) * 32 + nc) * 8;
            #pragma unroll
            for (int p = 0; p < 8; p++) add2(A[p], s[p]);
        }
        __syncthreads();
        if (kr == 1) {
            ULL* d = red + ((size_t)(bh * 2) * 32 + nc) * 8;
            #pragma unroll
            for (int p = 0; p < 8; p++) d[p] = A[p];
        }
        __syncthreads();
        if (kr == 0) {
            const ULL* s = red + ((size_t)(bh * 2) * 32 + nc) * 8;
            #pragma unroll
            for (int p = 0; p < 8; p++) add2(A[p], s[p]);
        }
    }

    if (kr == 0) {
        ULL* o0 = (ULL*)(outT + (size_t)(outcolbase + nc) * BATCH) + boff;
        ULL* o1 = (ULL*)(outT + (size_t)(outcolbase + nc + 32) * BATCH) + boff;
        #pragma unroll
        for (int p = 0; p < 8; p++) { o0[p] = acc0[p]; o1[p] = acc1[p]; }
    }
}

__global__ __launch_bounds__(GT, 3) void qkv_gemm_kernel(
    const float* __restrict__ Wq, const float* __restrict__ Wk,
    const float* __restrict__ Wv)
{
    const int tile  = blockIdx.x;          // 0..95
    const int split = blockIdx.y;          // 0..3
    const int ksz = DMODEL / SPLITS;       // 1024
    const int k0  = split * ksz;
    const float* W; int N, wcb, ocb;
    if (tile < 64)      { W = Wq; N = 4096; wcb = tile * 64;        ocb = tile * 64; }
    else if (tile < 80) { W = Wk; N = 1024; wcb = (tile - 64) * 64; ocb = 4096 + (tile - 64) * 64; }
    else                { W = Wv; N = 1024; wcb = (tile - 80) * 64; ocb = 5120 + (tile - 80) * 64; }
    gemm_body(g_xT, W, N, g_qkvT[split], wcb, ocb, k0, ksz);
}

__global__ __launch_bounds__(GT, 3) void wo_gemm_kernel(const float* __restrict__ Wo) {
    const int tile  = blockIdx.x;          // 0..63
    const int split = blockIdx.y;          // 0..3
    gemm_body(g_attnT, Wo, 4096, g_oT[split],
              tile * 64, tile * 64, split * 1024, 1024);
}

// ---------------- 3) split-sum + RoPE -------------------------------------
__global__ void rope_kernel(const int* __restrict__ ctx) {
    const int row = blockIdx.x;    // 0..31 q heads, 32..39 k heads, 40..47 v heads
    const int b   = blockIdx.y;
    const int j   = threadIdx.x;   // 0..63
    const int pos = ctx[b] - 1;

    int colbase;
    float* out;
    if (row < 32)      { colbase = row * HD;                 out = g_q    + (b * NH  + row)        * HD; }
    else if (row < 40) { colbase = 4096 + (row - 32) * HD;   out = g_knew + (b * NKV + (row - 32)) * HD; }
    else               { colbase = 5120 + (row - 40) * HD;   out = g_vnew + (b * NKV + (row - 40)) * HD; }

    float v0 = 0.f, v1 = 0.f;
    #pragma unroll
    for (int s = 0; s < SPLITS; s++) {
        v0 += g_qkvT[s][(colbase + j)      * BATCH + b];
        v1 += g_qkvT[s][(colbase + j + 64) * BATCH + b];
    }

    if (row < 40) {
        const float inv = exp2f(-(float)j * 0.20762050593046014f);
        const float ang = (float)pos * inv;
        float sn, cs;
        sincosf(ang, &sn, &cs);
        out[j]      = v0 * cs - v1 * sn;
        out[j + 64] = v0 * sn + v1 * cs;
    } else {
        out[j]      = v0;
        out[j + 64] = v1;
    }
}

// ---------------- 4) split-KV paged attention -----------------------------
// grid (chunk=16, kv=8, b=32) = 4096 CTAs, 128 threads = 4 warps.
// Lane layout: g = lane&3 (head within group), dg = lane>>2 (16 dims).
// Warp w processes 4-token tiles t0 + 4w + 16i + {0..3}; K/V staged to SMEM
// via cp.async double buffering (zero register staging, deep MLP).
// Score reduction: 3 SHFL (XOR 4/8/16) handles all 4 heads at once.
__global__ __launch_bounds__(128) void attn_kernel(
    const float* __restrict__ kcache, const float* __restrict__ vcache,
    const int* __restrict__ btab, const int* __restrict__ ctx)
{
    const int c  = blockIdx.x;
    const int kv = blockIdx.y;
    const int b  = blockIdx.z;
    const int tid  = threadIdx.x;
    const int wid  = tid >> 5;
    const int lane = tid & 31;
    const int g    = lane & 3;
    const int dg   = lane >> 2;

    const int len  = ctx[b];
    const int pos  = len - 1;
    const int t0   = (c * len) >> 4;          // NCHUNK = 16
    const int tend = ((c + 1) * len) >> 4;

    __shared__ int sbt[12];
    const int blk0 = t0 >> 4;
    if (tend > t0) {
        const int nblk = ((tend - 1) >> 4) - blk0 + 1;
        if (tid < nblk) sbt[tid] = btab[b * MAXBLK + blk0 + tid];
    }
    __syncthreads();

    // SMEM KV tiles: [warp][buf][token][K(32 float4) | V(32 float4)]
    __shared__ __align__(16) float4 skv[4][2][4][64];        // 32 KB
    __shared__ float smx[4][GQ], sl[4][GQ];
    __shared__ __align__(16) float sacc[4][GQ][HD];          // 8 KB

    // q for head g, dims dg*16 .. dg*16+15, packed as 8 f32x2
    ULL q2[8];
    {
        const float4* qb = (const float4*)(g_q + (size_t)(b * NH + kv * GQ + g) * HD);
        #pragma unroll
        for (int qi = 0; qi < 4; qi++) {
            const float4 v = qb[dg * 4 + qi];
            q2[2 * qi]     = pack2(v.x, v.y);
            q2[2 * qi + 1] = pack2(v.z, v.w);
        }
    }

    float m = -1e30f, l = 0.f;
    ULL acc2[8];
    #pragma unroll
    for (int p = 0; p < 8; p++) acc2[p] = 0ull;

    const float* knew = g_knew + (size_t)(b * NKV + kv) * HD;
    const float* vnew = g_vnew + (size_t)(b * NKV + kv) * HD;

    #define FILL(bufi, ii) do {                                              \
        const int tb_ = t0 + 4 * wid + 16 * (ii);                            \
        _Pragma("unroll")                                                    \
        for (int j_ = 0; j_ < 4; j_++) {                                     \
            const int t_ = tb_ + j_;                                         \
            if (t_ < tend) {                                                 \
                const float *kr_, *vr_;                                      \
                if (t_ == pos) { kr_ = knew; vr_ = vnew; }                   \
                else {                                                       \
                    const int slot_ = sbt[(t_ >> 4) - blk0] * BLKSZ + (t_ & 15); \
                    const size_t base_ = (size_t)slot_ * (NKV * HD) + (size_t)kv * HD; \
                    kr_ = kcache + base_; vr_ = vcache + base_;              \
                }                                                            \
                cpasync16(&skv[wid][bufi][j_][lane],      kr_ + lane * 4);   \
                cpasync16(&skv[wid][bufi][j_][32 + lane], vr_ + lane * 4);   \
            }                                                                \
        }                                                                    \
        cpcommit();                                                          \
    } while (0)

    FILL(0, 0);
    FILL(1, 1);

    for (int i = 0; ; i++) {
        const int tb = t0 + 4 * wid + 16 * i;
        if (tb >= tend) break;
        cpwait<1>();
        __syncwarp();
        const int buf = i & 1;

        #pragma unroll
        for (int j = 0; j < 4; j++) {
            if (tb + j >= tend) break;
            const float4* kp = &skv[wid][buf][j][dg * 4];
            ULL s2 = 0ull;
            #pragma unroll
            for (int qi = 0; qi < 4; qi++) {
                const float4 kx = kp[qi];
                ffma2(s2, pack2(kx.x, kx.y), q2[2 * qi]);
                ffma2(s2, pack2(kx.z, kx.w), q2[2 * qi + 1]);
            }
            float slo, shi;
            unpack2(s2, slo, shi);
            float s = slo + shi;
            s += __shfl_xor_sync(0xffffffffu, s, 4);
            s += __shfl_xor_sync(0xffffffffu, s, 8);
            s += __shfl_xor_sync(0xffffffffu, s, 16);
            s *= ATT_SCALE;

            const float mn = fmaxf(m, s);
            const float f = __expf(m - mn);
            const float p = __expf(s - mn);
            m = mn;
            l = l * f + p;

            const ULL f2 = bcast2(f);
            const ULL p2 = bcast2(p);
            const float4* vp = &skv[wid][buf][j][32 + dg * 4];
            #pragma unroll
            for (int qi = 0; qi < 4; qi++) {
                const float4 vx = vp[qi];
                acc2[2 * qi]     = fma2v(acc2[2 * qi],     f2, mul2(p2, pack2(vx.x, vx.y)));
                acc2[2 * qi + 1] = fma2v(acc2[2 * qi + 1], f2, mul2(p2, pack2(vx.z, vx.w)));
            }
        }
        __syncwarp();
        FILL(buf, i + 2);
    }
    cpwait<0>();
    #undef FILL

    // write warp-local state
    if (dg == 0) { smx[wid][g] = m; sl[wid][g] = l; }
    {
        float4* dst = (float4*)&sacc[wid][g][dg * 16];
        #pragma unroll
        for (int qi = 0; qi < 4; qi++) {
            float4 o;
            unpack2(acc2[2 * qi],     o.x, o.y);
            unpack2(acc2[2 * qi + 1], o.z, o.w);
            dst[qi] = o;
        }
    }
    __syncthreads();

    // CTA merge across 4 warps
    const int d = tid;   // 128 threads == HD
    #pragma unroll
    for (int gg = 0; gg < GQ; gg++) {
        float ms = -1e30f;
        #pragma unroll
        for (int w = 0; w < 4; w++) ms = fmaxf(ms, smx[w][gg]);
        float L = 0.f, A = 0.f;
        #pragma unroll
        for (int w = 0; w < 4; w++) {
            const float f = __expf(smx[w][gg] - ms);
            L += sl[w][gg] * f;
            A += sacc[w][gg][d] * f;
        }
        const int pidx = ((b * NH + kv * GQ + gg) * NCHUNK + c);
        g_pacc[(size_t)pidx * HD + d] = A;
        if (d == 0) { g_pm[pidx] = ms; g_pl[pidx] = L; }
    }
}

// combine 16 chunk partials per (b,h); write attnT for the Wo GEMM
__global__ __launch_bounds__(HD) void attn_combine_kernel() {
    const int bh = blockIdx.x;        // 0..1023
    const int d  = threadIdx.x;       // 0..127
    float ms = -1e30f;
    #pragma unroll
    for (int c = 0; c < NCHUNK; c++) ms = fmaxf(ms, g_pm[bh * NCHUNK + c]);
    float L = 0.f, A = 0.f;
    #pragma unroll
    for (int c = 0; c < NCHUNK; c++) {
        const float f = __expf(g_pm[bh * NCHUNK + c] - ms);
        L += g_pl[bh * NCHUNK + c] * f;
        A += g_pacc[(size_t)(bh * NCHUNK + c) * HD + d] * f;
    }
    const float o = A / L;
    const int b = bh >> 5;
    const int h = bh & 31;
    g_attnT[(size_t)(h * HD + d) * BATCH + b] = o;
}

// ---------------- 5) sum Wo split partials -> d_out -----------------------
__global__ void out_combine_kernel(float* __restrict__ out) {
    const int i = blockIdx.x * 256 + threadIdx.x;   // 131072 total
    const int n = i >> 5;
    const int b = i & 31;
    float v = 0.f;
    #pragma unroll
    for (int s = 0; s < SPLITS; s++) v += g_oT[s][(size_t)n * BATCH + b];
    out[(size_t)b * DMODEL + n] = v;
}

// ---------------- launcher -------------------------------------------------
extern "C" void kernel_launch(void* const* d_in, const int* in_sizes, int n_in,
                              void* d_out, int out_size) {
    const float* x   = (const float*)d_in[0];
    const float* Wq  = (const float*)d_in[1];
    const float* Wk  = (const float*)d_in[2];
    const float* Wv  = (const float*)d_in[3];
    const float* Wo  = (const float*)d_in[4];
    const float* kc  = (const float*)d_in[5];
    const float* vc  = (const float*)d_in[6];
    const int*   bt  = (const int*)d_in[7];
    const int*   ctx = (const int*)d_in[8];
    float* out = (float*)d_out;

    transpose_x_kernel<<<DMODEL / 32, dim3(32, 8)>>>(x);
    qkv_gemm_kernel<<<dim3(96, SPLITS), GT>>>(Wq, Wk, Wv);
    rope_kernel<<<dim3(48, BATCH), 64>>>(ctx);
    attn_kernel<<<dim3(NCHUNK, NKV, BATCH), 128>>>(kc, vc, bt, ctx);
    attn_combine_kernel<<<BATCH * NH, HD>>>();
    wo_gemm_kernel<<<dim3(64, SPLITS), GT>>>(Wo);
    out_combine_kernel<<<(BATCH * DMODEL) / 256, 256>>>(out);
}

// round 16
// speedup vs baseline: 1.3701x; 1.3701x over previous
#include <cuda_runtime.h>
#include <math.h>

// ---------------- problem constants ----------------
#define BATCH   32
#define DMODEL  4096
#define NH      32
#define NKV     8
#define GQ      4           // NH / NKV
#define HD      128
#define MAXSEQ  2048
#define BLKSZ   16
#define MAXBLK  128         // MAXSEQ / BLKSZ
#define ATT_SCALE 0.08838834764831845f   // 128^-0.5

#define NQKV    (NH*HD + 2*NKV*HD)       // 6144
#define SPLITS  4
#define NCHUNK  16

typedef unsigned long long ULL;

// ---------------- scratch (device globals; no allocation allowed) --------
__device__ __align__(16) float g_xT[DMODEL * BATCH];
__device__ __align__(16) float g_qkvT[SPLITS][NQKV * BATCH];
__device__ __align__(16) float g_q[BATCH * NH * HD];
__device__ __align__(16) float g_knew[BATCH * NKV * HD];
__device__ __align__(16) float g_vnew[BATCH * NKV * HD];
__device__ float g_pm[BATCH * NH * NCHUNK];
__device__ float g_pl[BATCH * NH * NCHUNK];
__device__ __align__(16) float g_pacc[BATCH * NH * NCHUNK * HD];
__device__ __align__(16) float g_attnT[DMODEL * BATCH];
__device__ __align__(16) float g_oT[SPLITS][DMODEL * BATCH];

// ---------------- packed f32x2 helpers (sm_103a) --------------------------
__device__ __forceinline__ void ffma2(ULL& acc, ULL a, ULL b) {
    asm("fma.rn.f32x2 %0, %1, %2, %3;" : "=l"(acc) : "l"(a), "l"(b), "l"(acc));
}
__device__ __forceinline__ ULL fma2v(ULL a, ULL b, ULL c) {   // a*b + c
    ULL d; asm("fma.rn.f32x2 %0, %1, %2, %3;" : "=l"(d) : "l"(a), "l"(b), "l"(c));
    return d;
}
__device__ __forceinline__ ULL mul2(ULL a, ULL b) {
    ULL d; asm("mul.rn.f32x2 %0, %1, %2;" : "=l"(d) : "l"(a), "l"(b));
    return d;
}
__device__ __forceinline__ ULL bcast2(float w) {
    ULL r; asm("mov.b64 %0, {%1, %1};" : "=l"(r) : "r"(__float_as_uint(w)));
    return r;
}
__device__ __forceinline__ void add2(ULL& a, ULL b) {
    asm("add.rn.f32x2 %0, %1, %2;" : "=l"(a) : "l"(a), "l"(b));
}
__device__ __forceinline__ ULL pack2(float a, float b) {
    ULL r; asm("mov.b64 %0, {%1, %2};" : "=l"(r)
               : "r"(__float_as_uint(a)), "r"(__float_as_uint(b)));
    return r;
}
__device__ __forceinline__ void unpack2(ULL v, float& a, float& b) {
    unsigned int x, y;
    asm("mov.b64 {%0, %1}, %2;" : "=r"(x), "=r"(y) : "l"(v));
    a = __uint_as_float(x); b = __uint_as_float(y);
}

// ---------------- cp.async helpers ----------------------------------------
__device__ __forceinline__ void cpasync16(void* smem, const void* gmem) {
    unsigned int s = (unsigned int)__cvta_generic_to_shared(smem);
    asm volatile("cp.async.cg.shared.global [%0], [%1], 16;" :: "r"(s), "l"(gmem));
}
__device__ __forceinline__ void cpcommit() {
    asm volatile("cp.async.commit_group;");
}
template<int N> __device__ __forceinline__ void cpwait() {
    asm volatile("cp.async.wait_group %0;" :: "n"(N));
}

// ---------------- 1) transpose x (32 x 4096) -> xT (4096 x 32) -----------
__global__ void transpose_x_kernel(const float* __restrict__ x) {
    __shared__ float tile[32][33];
    int k0 = blockIdx.x * 32;
    int tx = threadIdx.x;            // 0..31
    int ty = threadIdx.y;            // 0..7
    #pragma unroll
    for (int r = ty; r < 32; r += 8)
        tile[r][tx] = x[r * DMODEL + k0 + tx];
    __syncthreads();
    #pragma unroll
    for (int r = ty; r < 32; r += 8)
        g_xT[(k0 + r) * BATCH + tx] = tile[tx][r];
}

// ---------------- 2) GEMM: Y(32 x N) = x(32 x K) @ W(K x N) --------------
// cp.async double-buffered W/x tiles in SMEM (no redundant weight LDGs,
// deep MLP, low register pressure). CTA: 64 cols x 1024-k split, 256 thr.
// thread = (nc 0..31, kr 0..3, bh 0..1): cols n0=base+nc, n0+32;
// batches bh*16..+15 as 8 f32x2 pairs; k-rows kr+4i.
#define GT  256
#define GKB 64      // k-rows per buffer step

__device__ __forceinline__ void gemm_body(
    const float* __restrict__ xT, const float* __restrict__ W, int N,
    float* __restrict__ outT, int wcolbase, int outcolbase,
    int k0, int ksz)
{
    __shared__ __align__(16) float ws[2][GKB][64];    // 32 KB
    __shared__ __align__(16) float xsm[2][GKB][32];   // 16 KB
    __shared__ ULL red[2 * 2 * 32 * 8];               //  8 KB

    const int tid = threadIdx.x;
    const int nc = tid & 31;
    const int kr = (tid >> 5) & 3;
    const int bh = tid >> 7;          // 0 or 1
    const int nsteps = ksz / GKB;     // 16

    ULL acc0[8], acc1[8];
    #pragma unroll
    for (int p = 0; p < 8; p++) { acc0[p] = 0ull; acc1[p] = 0ull; }

    #define GFILL(bufi, step) do {                                           \
        if ((step) < nsteps) {                                               \
            const int kb_ = k0 + (step) * GKB;                               \
            _Pragma("unroll")                                                \
            for (int r_ = 0; r_ < 4; r_++) {                                 \
                const int ch_ = tid + 256 * r_;                              \
                const int row_ = ch_ >> 4, co_ = (ch_ & 15) * 4;             \
                cpasync16(&ws[bufi][row_][co_],                              \
                          W + (size_t)(kb_ + row_) * N + wcolbase + co_);    \
            }                                                                \
            _Pragma("unroll")                                                \
            for (int r_ = 0; r_ < 2; r_++) {                                 \
                const int ch_ = tid + 256 * r_;                              \
                const int row_ = ch_ >> 3, co_ = (ch_ & 7) * 4;              \
                cpasync16(&xsm[bufi][row_][co_],                             \
                          xT + (size_t)(kb_ + row_) * 32 + co_);             \
            }                                                                \
        }                                                                    \
        cpcommit();                                                          \
    } while (0)

    GFILL(0, 0);
    GFILL(1, 1);

    for (int s = 0; s < nsteps; s++) {
        cpwait<1>();
        __syncthreads();
        const int buf = s & 1;

        #pragma unroll
        for (int i = 0; i < GKB / 4; i++) {
            const int kl = kr + 4 * i;
            const ULL w0p = bcast2(ws[buf][kl][nc]);
            const ULL w1p = bcast2(ws[buf][kl][nc + 32]);
            const float4* xr4 = (const float4*)(&xsm[buf][kl][bh * 16]);
            float4 xv0 = xr4[0], xv1 = xr4[1], xv2 = xr4[2], xv3 = xr4[3];
            ULL xp[8];
            xp[0] = pack2(xv0.x, xv0.y); xp[1] = pack2(xv0.z, xv0.w);
            xp[2] = pack2(xv1.x, xv1.y); xp[3] = pack2(xv1.z, xv1.w);
            xp[4] = pack2(xv2.x, xv2.y); xp[5] = pack2(xv2.z, xv2.w);
            xp[6] = pack2(xv3.x, xv3.y); xp[7] = pack2(xv3.z, xv3.w);
            #pragma unroll
            for (int p = 0; p < 8; p++) {
                ffma2(acc0[p], xp[p], w0p);
                ffma2(acc1[p], xp[p], w1p);
            }
        }
        __syncthreads();
        GFILL(buf, s + 2);
    }
    cpwait<0>();
    #undef GFILL

    // reduce over kr (4 partials) via smem, for acc0 then acc1
    #pragma unroll
    for (int half = 0; half < 2; half++) {
        ULL* A = half ? acc1 : acc0;
        __syncthreads();
        if (kr >= 2) {
            ULL* d = red + ((size_t)(bh * 2 + (kr - 2)) * 32 + nc) * 8;
            #pragma unroll
            for (int p = 0; p < 8; p++) d[p] = A[p];
        }
        __syncthreads();
        if (kr < 2) {
            const ULL* s = red + ((size_t)(bh * 2 + kr) * 32 + nc) * 8;
            #pragma unroll
            for (int p = 0; p < 8; p++) add2(A[p], s[p]);
        }
        __syncthreads();
        if (kr == 1) {
            ULL* d = red + ((size_t)(bh * 2) * 32 + nc) * 8;
            #pragma unroll
            for (int p = 0; p < 8; p++) d[p] = A[p];
        }
        __syncthreads();
        if (kr == 0) {
            const ULL* s = red + ((size_t)(bh * 2) * 32 + nc) * 8;
            #pragma unroll
            for (int p = 0; p < 8; p++) add2(A[p], s[p]);
        }
    }

    if (kr == 0) {
        ULL* o0 = (ULL*)(outT + (size_t)(outcolbase + nc) * BATCH) + bh * 8;
        ULL* o1 = (ULL*)(outT + (size_t)(outcolbase + nc + 32) * BATCH) + bh * 8;
        #pragma unroll
        for (int p = 0; p < 8; p++) { o0[p] = acc0[p]; o1[p] = acc1[p]; }
    }
}

__global__ __launch_bounds__(GT, 4) void qkv_gemm_kernel(
    const float* __restrict__ Wq, const float* __restrict__ Wk,
    const float* __restrict__ Wv)
{
    const int tile  = blockIdx.x;          // 0..95
    const int split = blockIdx.y;          // 0..3
    const int ksz = DMODEL / SPLITS;       // 1024
    const int k0  = split * ksz;
    const float* W; int N, wcb, ocb;
    if (tile < 64)      { W = Wq; N = 4096; wcb = tile * 64;        ocb = tile * 64; }
    else if (tile < 80) { W = Wk; N = 1024; wcb = (tile - 64) * 64; ocb = 4096 + (tile - 64) * 64; }
    else                { W = Wv; N = 1024; wcb = (tile - 80) * 64; ocb = 5120 + (tile - 80) * 64; }
    gemm_body(g_xT, W, N, g_qkvT[split], wcb, ocb, k0, ksz);
}

__global__ __launch_bounds__(GT, 4) void wo_gemm_kernel(const float* __restrict__ Wo) {
    const int tile  = blockIdx.x;          // 0..63
    const int split = blockIdx.y;          // 0..3
    gemm_body(g_attnT, Wo, 4096, g_oT[split],
              tile * 64, tile * 64, split * 1024, 1024);
}

// ---------------- 3) split-sum + RoPE -------------------------------------
__global__ void rope_kernel(const int* __restrict__ ctx) {
    const int row = blockIdx.x;    // 0..31 q heads, 32..39 k heads, 40..47 v heads
    const int b   = blockIdx.y;
    const int j   = threadIdx.x;   // 0..63
    const int pos = ctx[b] - 1;

    int colbase;
    float* out;
    if (row < 32)      { colbase = row * HD;                 out = g_q    + (b * NH  + row)        * HD; }
    else if (row < 40) { colbase = 4096 + (row - 32) * HD;   out = g_knew + (b * NKV + (row - 32)) * HD; }
    else               { colbase = 5120 + (row - 40) * HD;   out = g_vnew + (b * NKV + (row - 40)) * HD; }

    float v0 = 0.f, v1 = 0.f;
    #pragma unroll
    for (int s = 0; s < SPLITS; s++) {
        v0 += g_qkvT[s][(colbase + j)      * BATCH + b];
        v1 += g_qkvT[s][(colbase + j + 64) * BATCH + b];
    }

    if (row < 40) {
        const float inv = exp2f(-(float)j * 0.20762050593046014f);
        const float ang = (float)pos * inv;
        float sn, cs;
        sincosf(ang, &sn, &cs);
        out[j]      = v0 * cs - v1 * sn;
        out[j + 64] = v0 * sn + v1 * cs;
    } else {
        out[j]      = v0;
        out[j + 64] = v1;
    }
}

// ---------------- 4) split-KV paged attention -----------------------------
// grid (chunk=16, kv=8, b=32) = 4096 CTAs, 128 threads = 4 warps.
// Lane layout: g = lane&3 (head), dg = lane>>2 (16 dims). cp.async
// double-buffered 4-token K/V tiles per warp. Tile softmax: one rescale
// per 4 tokens. sacc aliased into skv (disjoint lifetimes) -> 33 KB smem
// -> 6 CTAs/SM.
__global__ __launch_bounds__(128, 6) void attn_kernel(
    const float* __restrict__ kcache, const float* __restrict__ vcache,
    const int* __restrict__ btab, const int* __restrict__ ctx)
{
    const int c  = blockIdx.x;
    const int kv = blockIdx.y;
    const int b  = blockIdx.z;
    const int tid  = threadIdx.x;
    const int wid  = tid >> 5;
    const int lane = tid & 31;
    const int g    = lane & 3;
    const int dg   = lane >> 2;

    const int len  = ctx[b];
    const int pos  = len - 1;
    const int t0   = (c * len) >> 4;          // NCHUNK = 16
    const int tend = ((c + 1) * len) >> 4;

    __shared__ int sbt[12];
    const int blk0 = t0 >> 4;
    if (tend > t0) {
        const int nblk = ((tend - 1) >> 4) - blk0 + 1;
        if (tid < nblk) sbt[tid] = btab[b * MAXBLK + blk0 + tid];
    }
    __syncthreads();

    // [warp][buf][token][K(32 float4) | V(32 float4)]  (32 KB)
    __shared__ __align__(16) float4 skv[4][2][4][64];
    __shared__ float smx[4][GQ], sl[4][GQ];
    float* sacc = (float*)skv;                 // aliased: [w][g][d]

    ULL q2[8];
    {
        const float4* qb = (const float4*)(g_q + (size_t)(b * NH + kv * GQ + g) * HD);
        #pragma unroll
        for (int qi = 0; qi < 4; qi++) {
            const float4 v = qb[dg * 4 + qi];
            q2[2 * qi]     = pack2(v.x, v.y);
            q2[2 * qi + 1] = pack2(v.z, v.w);
        }
    }

    float m = -1e30f, l = 0.f;
    ULL acc2[8];
    #pragma unroll
    for (int p = 0; p < 8; p++) acc2[p] = 0ull;

    const float* knew = g_knew + (size_t)(b * NKV + kv) * HD;
    const float* vnew = g_vnew + (size_t)(b * NKV + kv) * HD;

    #define FILL(bufi, ii) do {                                              \
        const int tb_ = t0 + 4 * wid + 16 * (ii);                            \
        _Pragma("unroll")                                                    \
        for (int j_ = 0; j_ < 4; j_++) {                                     \
            const int t_ = tb_ + j_;                                         \
            if (t_ < tend) {                                                 \
                const float *kr_, *vr_;                                      \
                if (t_ == pos) { kr_ = knew; vr_ = vnew; }                   \
                else {                                                       \
                    const int slot_ = sbt[(t_ >> 4) - blk0] * BLKSZ + (t_ & 15); \
                    const size_t base_ = (size_t)slot_ * (NKV * HD) + (size_t)kv * HD; \
                    kr_ = kcache + base_; vr_ = vcache + base_;              \
                }                                                            \
                cpasync16(&skv[wid][bufi][j_][lane],      kr_ + lane * 4);   \
                cpasync16(&skv[wid][bufi][j_][32 + lane], vr_ + lane * 4);   \
            }                                                                \
        }                                                                    \
        cpcommit();                                                          \
    } while (0)

    FILL(0, 0);
    FILL(1, 1);

    for (int i = 0; ; i++) {
        const int tb = t0 + 4 * wid + 16 * i;
        if (tb >= tend) break;
        cpwait<1>();
        __syncwarp();
        const int buf = i & 1;
        const int cnt = min(tend - tb, 4);

        // scores for up to 4 tokens
        float s[4];
        #pragma unroll
        for (int j = 0; j < 4; j++) {
            const float4* kp = &skv[wid][buf][j][dg * 4];
            ULL s2 = 0ull;
            #pragma unroll
            for (int qi = 0; qi < 4; qi++) {
                const float4 kx = kp[qi];
                ffma2(s2, pack2(kx.x, kx.y), q2[2 * qi]);
                ffma2(s2, pack2(kx.z, kx.w), q2[2 * qi + 1]);
            }
            float slo, shi;
            unpack2(s2, slo, shi);
            float ss = slo + shi;
            ss += __shfl_xor_sync(0xffffffffu, ss, 4);
            ss += __shfl_xor_sync(0xffffffffu, ss, 8);
            ss += __shfl_xor_sync(0xffffffffu, ss, 16);
            s[j] = (j < cnt) ? ss * ATT_SCALE : -1e30f;
        }

        // tile softmax: one rescale per 4 tokens
        float mt = fmaxf(fmaxf(s[0], s[1]), fmaxf(s[2], s[3]));
        mt = fmaxf(mt, m);
        const float f = __expf(m - mt);
        float p[4];
        #pragma unroll
        for (int j = 0; j < 4; j++) p[j] = __expf(s[j] - mt);
        m = mt;
        l = l * f + (p[0] + p[1]) + (p[2] + p[3]);

        const ULL f2 = bcast2(f);
        #pragma unroll
        for (int pp = 0; pp < 8; pp++) acc2[pp] = mul2(acc2[pp], f2);

        #pragma unroll
        for (int j = 0; j < 4; j++) {
            if (j >= cnt) break;
            const ULL p2 = bcast2(p[j]);
            const float4* vp = &skv[wid][buf][j][32 + dg * 4];
            #pragma unroll
            for (int qi = 0; qi < 4; qi++) {
                const float4 vx = vp[qi];
                acc2[2 * qi]     = fma2v(p2, pack2(vx.x, vx.y), acc2[2 * qi]);
                acc2[2 * qi + 1] = fma2v(p2, pack2(vx.z, vx.w), acc2[2 * qi + 1]);
            }
        }
        __syncwarp();
        FILL(buf, i + 2);
    }
    cpwait<0>();
    #undef FILL

    if (dg == 0) { smx[wid][g] = m; sl[wid][g] = l; }
    __syncthreads();          // all warps done with skv before aliased writes

    {
        float4* dst = (float4*)&sacc[((wid * GQ + g) * HD) + dg * 16];
        #pragma unroll
        for (int qi = 0; qi < 4; qi++) {
            float4 o;
            unpack2(acc2[2 * qi],     o.x, o.y);
            unpack2(acc2[2 * qi + 1], o.z, o.w);
            dst[qi] = o;
        }
    }
    __syncthreads();

    // CTA merge across 4 warps
    const int d = tid;   // 128 threads == HD
    #pragma unroll
    for (int gg = 0; gg < GQ; gg++) {
        float ms = -1e30f;
        #pragma unroll
        for (int w = 0; w < 4; w++) ms = fmaxf(ms, smx[w][gg]);
        float L = 0.f, A = 0.f;
        #pragma unroll
        for (int w = 0; w < 4; w++) {
            const float f = __expf(smx[w][gg] - ms);
            L += sl[w][gg] * f;
            A += sacc[(w * GQ + gg) * HD + d] * f;
        }
        const int pidx = ((b * NH + kv * GQ + gg) * NCHUNK + c);
        g_pacc[(size_t)pidx * HD + d] = A;
        if (d == 0) { g_pm[pidx] = ms; g_pl[pidx] = L; }
    }
}

// combine 16 chunk partials per (b,h); write attnT for the Wo GEMM
__global__ __launch_bounds__(HD) void attn_combine_kernel() {
    const int bh = blockIdx.x;        // 0..1023
    const int d  = threadIdx.x;       // 0..127
    float ms = -1e30f;
    #pragma unroll
    for (int c = 0; c < NCHUNK; c++) ms = fmaxf(ms, g_pm[bh * NCHUNK + c]);
    float L = 0.f, A = 0.f;
    #pragma unroll
    for (int c = 0; c < NCHUNK; c++) {
        const float f = __expf(g_pm[bh * NCHUNK + c] - ms);
        L += g_pl[bh * NCHUNK + c] * f;
        A += g_pacc[(size_t)(bh * NCHUNK + c) * HD + d] * f;
    }
    const float o = A / L;
    const int b = bh >> 5;
    const int h = bh & 31;
    g_attnT[(size_t)(h * HD + d) * BATCH + b] = o;
}

// ---------------- 5) sum Wo split partials -> d_out -----------------------
__global__ void out_combine_kernel(float* __restrict__ out) {
    const int i = blockIdx.x * 256 + threadIdx.x;   // 131072 total
    const int n = i >> 5;
    const int b = i & 31;
    float v = 0.f;
    #pragma unroll
    for (int s = 0; s < SPLITS; s++) v += g_oT[s][(size_t)n * BATCH + b];
    out[(size_t)b * DMODEL + n] = v;
}

// ---------------- launcher -------------------------------------------------
extern "C" void kernel_launch(void* const* d_in, const int* in_sizes, int n_in,
                              void* d_out, int out_size) {
    const float* x   = (const float*)d_in[0];
    const float* Wq  = (const float*)d_in[1];
    const float* Wk  = (const float*)d_in[2];
    const float* Wv  = (const float*)d_in[3];
    const float* Wo  = (const float*)d_in[4];
    const float* kc  = (const float*)d_in[5];
    const float* vc  = (const float*)d_in[6];
    const int*   bt  = (const int*)d_in[7];
    const int*   ctx = (const int*)d_in[8];
    float* out = (float*)d_out;

    transpose_x_kernel<<<DMODEL / 32, dim3(32, 8)>>>(x);
    qkv_gemm_kernel<<<dim3(96, SPLITS), GT>>>(Wq, Wk, Wv);
    rope_kernel<<<dim3(48, BATCH), 64>>>(ctx);
    attn_kernel<<<dim3(NCHUNK, NKV, BATCH), 128>>>(kc, vc, bt, ctx);
    attn_combine_kernel<<<BATCH * NH, HD>>>();
    wo_gemm_kernel<<<dim3(64, SPLITS), GT>>>(Wo);
    out_combine_kernel<<<(BATCH * DMODEL) / 256, 256>>>(out);
}